// round 11
// baseline (speedup 1.0000x reference)
#include <cuda_runtime.h>
#include <math.h>

#define IMG_W 512
#define IMG_H 512

// AAN (Arai-Agui-Nakajima) 8-point forward DCT, libjpeg jfdctflt flowgraph.
__device__ __forceinline__ void aan_dct8(float* d)
{
    float tmp0 = d[0] + d[7], tmp7 = d[0] - d[7];
    float tmp1 = d[1] + d[6], tmp6 = d[1] - d[6];
    float tmp2 = d[2] + d[5], tmp5 = d[2] - d[5];
    float tmp3 = d[3] + d[4], tmp4 = d[3] - d[4];

    float tmp10 = tmp0 + tmp3, tmp13 = tmp0 - tmp3;
    float tmp11 = tmp1 + tmp2, tmp12 = tmp1 - tmp2;

    d[0] = tmp10 + tmp11;
    d[4] = tmp10 - tmp11;

    float z1 = (tmp12 + tmp13) * 0.707106781f;
    d[2] = tmp13 + z1;
    d[6] = tmp13 - z1;

    tmp10 = tmp4 + tmp5;
    tmp11 = tmp5 + tmp6;
    tmp12 = tmp6 + tmp7;

    float z5 = (tmp10 - tmp12) * 0.382683433f;
    float z2 = fmaf(0.541196100f, tmp10, z5);
    float z4 = fmaf(1.306562965f, tmp12, z5);
    float z3 = tmp11 * 0.707106781f;

    float z11 = tmp7 + z3;
    float z13 = tmp7 - z3;

    d[5] = z13 + z2;
    d[3] = z13 - z2;
    d[1] = z11 + z4;
    d[7] = z11 - z4;
}

// In-register 8x8 transpose across an 8-lane group (12 shfl butterflies).
__device__ __forceinline__ void transpose8(float* d, int x)
{
    #pragma unroll
    for (int m = 1; m < 8; m <<= 1) {
        #pragma unroll
        for (int j0 = 0; j0 < 8; j0++) {
            if (j0 & m) continue;
            int j1 = j0 | m;
            float a   = (x & m) ? d[j0] : d[j1];
            float bsh = __shfl_xor_sync(0xffffffffu, a, m);
            if (x & m) d[j0] = bsh; else d[j1] = bsh;
        }
    }
}

__constant__ int c_yt[64] = {
    16,11,10,16,24,40,51,61, 12,12,14,19,26,58,60,55,
    14,13,16,24,40,57,69,56, 14,17,22,29,51,87,80,62,
    18,22,37,56,68,109,103,77, 24,35,55,64,81,104,113,92,
    49,64,78,87,103,121,120,101, 72,92,95,98,112,100,103,99};
__constant__ int c_ct[64] = {
    17,18,24,47,99,99,99,99, 18,21,26,66,99,99,99,99,
    24,26,56,99,99,99,99,99, 47,66,99,99,99,99,99,99,
    99,99,99,99,99,99,99,99, 99,99,99,99,99,99,99,99,
    99,99,99,99,99,99,99,99, 99,99,99,99,99,99,99,99};
__constant__ float c_asf[8] = {
    1.0f, 1.3870398453f, 1.3065629649f, 1.1758756024f,
    1.0f, 0.7856949583f, 0.5411961001f, 0.2758993792f};

// One CTA: 128(W) x 16(H) tile. 32 groups of 8 lanes; group g owns Y block
// (by = g>>4, bx = g&15), lane x owns row x of that block — Y path is
// register-only (no smem). Chroma pools into a 4.4KB smem buffer.
__global__ void __launch_bounds__(256)
jpeg_compress_kernel(const float* __restrict__ img, float* __restrict__ out)
{
    __shared__ float sCbP[8][68];   // pooled Cb (centered), 64 wide + pad
    __shared__ float sCrP[8][68];   // pooled Cr
    __shared__ float sQ  [128];     // quant reciprocal tables

    const int t       = threadIdx.x;
    const int tileCol = blockIdx.x;   // 0..3   (128-px cols)
    const int tileRow = blockIdx.y;   // 0..31  (16-px rows)
    const int b       = blockIdx.z;
    const int nbatch  = gridDim.z;

    if (t < 64) {
        int uu = t >> 3, vv = t & 7;
        float sc = 1.0f / (8.0f * c_asf[uu] * c_asf[vv]);
        sQ[t]      = sc / (float)c_yt[t];
        sQ[64 + t] = sc / (float)c_ct[t];
    }
    // sQ is read by ALL threads in phase 3a (which runs before the main
    // barrier), so it must be published before any thread proceeds.
    __syncthreads();

    const int g  = t >> 3;          // group 0..31
    const int x  = t & 7;           // lane within group = row within block
    const int by = g >> 4;          // 0..1
    const int bx = g & 15;          // 0..15

    // --- Phase 1: direct block-layout loads (6 independent LDG.128) ---
    const size_t plane = (size_t)IMG_H * IMG_W;
    const float* p0 = img + (size_t)b * 3 * plane
                    + (size_t)(tileRow * 16 + by * 8 + x) * IMG_W
                    + tileCol * 128 + bx * 8;
    const float4 Ra = *reinterpret_cast<const float4*>(p0);
    const float4 Rb = *reinterpret_cast<const float4*>(p0 + 4);
    const float4 Ga = *reinterpret_cast<const float4*>(p0 + plane);
    const float4 Gb = *reinterpret_cast<const float4*>(p0 + plane + 4);
    const float4 Ba = *reinterpret_cast<const float4*>(p0 + 2 * plane);
    const float4 Bb = *reinterpret_cast<const float4*>(p0 + 2 * plane + 4);

    float Rv[8] = {Ra.x,Ra.y,Ra.z,Ra.w, Rb.x,Rb.y,Rb.z,Rb.w};
    float Gv[8] = {Ga.x,Ga.y,Ga.z,Ga.w, Gb.x,Gb.y,Gb.z,Gb.w};
    float Bv[8] = {Ba.x,Ba.y,Ba.z,Ba.w, Bb.x,Bb.y,Bb.z,Bb.w};

    float d[8], cbv[8], crv[8];
    #pragma unroll
    for (int i = 0; i < 8; i++) {
        float R = Rv[i] * 255.0f;
        float G = Gv[i] * 255.0f;
        float B = Bv[i] * 255.0f;
        d  [i] =  0.299f    * R + 0.587f    * G + 0.114f    * B - 128.0f;
        cbv[i] = -0.168736f * R - 0.331264f * G + 0.5f      * B;
        crv[i] =  0.5f      * R - 0.418688f * G - 0.081312f * B;
    }

    // --- Phase 2: chroma 2x2 pool. Horizontal pairs in-thread, vertical via
    //     shfl with lane x^1 (adjacent image row). Even lanes write float4. ---
    {
        float h0 = cbv[0]+cbv[1], h1 = cbv[2]+cbv[3], h2 = cbv[4]+cbv[5], h3 = cbv[6]+cbv[7];
        float k0 = crv[0]+crv[1], k1 = crv[2]+crv[3], k2 = crv[4]+crv[5], k3 = crv[6]+crv[7];
        h0 += __shfl_xor_sync(0xffffffffu, h0, 1);
        h1 += __shfl_xor_sync(0xffffffffu, h1, 1);
        h2 += __shfl_xor_sync(0xffffffffu, h2, 1);
        h3 += __shfl_xor_sync(0xffffffffu, h3, 1);
        k0 += __shfl_xor_sync(0xffffffffu, k0, 1);
        k1 += __shfl_xor_sync(0xffffffffu, k1, 1);
        k2 += __shfl_xor_sync(0xffffffffu, k2, 1);
        k3 += __shfl_xor_sync(0xffffffffu, k3, 1);
        if (!(x & 1)) {
            int pr = by * 4 + (x >> 1);   // pooled row 0..7
            int pc = bx * 4;              // pooled col base
            *reinterpret_cast<float4*>(&sCbP[pr][pc]) =
                make_float4(0.25f*h0, 0.25f*h1, 0.25f*h2, 0.25f*h3);
            *reinterpret_cast<float4*>(&sCrP[pr][pc]) =
                make_float4(0.25f*k0, 0.25f*k1, 0.25f*k2, 0.25f*k3);
        }
    }

    // --- Phase 3a: Y DCT + store, fully in registers, BEFORE the barrier ---
    {
        aan_dct8(d);
        transpose8(d, x);
        aan_dct8(d);

        const int v = x;
        int n = (tileRow * 2 + by) * 64 + (tileCol * 16 + bx);
        float* dst = out + (size_t)b * 4096 * 64 + (size_t)n * 64 + v;
        #pragma unroll
        for (int u = 0; u < 8; u++)
            dst[u * 8] = rintf(d[u] * sQ[u * 8 + v]);
    }

    __syncthreads();

    // --- Phase 3b: chroma DCT (16 groups: 8 Cb + 8 Cr; warps 0-3 active) ---
    if (g < 16) {
        const int comp = g >> 3;          // 0 = Cb, 1 = Cr
        const int bxc  = g & 7;           // 0..7
        const float (*src)[68] = comp ? sCrP : sCbP;

        float e[8];
        float4 a = *reinterpret_cast<const float4*>(&src[x][bxc * 8]);
        float4 c = *reinterpret_cast<const float4*>(&src[x][bxc * 8 + 4]);
        e[0]=a.x; e[1]=a.y; e[2]=a.z; e[3]=a.w;
        e[4]=c.x; e[5]=c.y; e[6]=c.z; e[7]=c.w;

        aan_dct8(e);
        transpose8(e, x);
        aan_dct8(e);

        const int v = x;
        int n = tileRow * 32 + tileCol * 8 + bxc;
        size_t off = (size_t)nbatch * 4096 * 64
                   + (size_t)comp * nbatch * 1024 * 64
                   + (size_t)b * 1024 * 64 + (size_t)n * 64;
        float* dst = out + off + v;
        #pragma unroll
        for (int u = 0; u < 8; u++)
            dst[u * 8] = rintf(e[u] * sQ[64 + u * 8 + v]);
    }
}

extern "C" void kernel_launch(void* const* d_in, const int* in_sizes, int n_in,
                              void* d_out, int out_size)
{
    const float* img = (const float*)d_in[0];
    float* out = (float*)d_out;
    int nbatch = in_sizes[0] / (3 * IMG_H * IMG_W);
    dim3 grid(IMG_W / 128, IMG_H / 16, nbatch);
    jpeg_compress_kernel<<<grid, 256>>>(img, out);
}

// round 12
// speedup vs baseline: 1.4677x; 1.4677x over previous
#include <cuda_runtime.h>
#include <math.h>

#define IMG_W 512
#define IMG_H 512

// AAN (Arai-Agui-Nakajima) 8-point forward DCT, libjpeg jfdctflt flowgraph.
__device__ __forceinline__ void aan_dct8(float* d)
{
    float tmp0 = d[0] + d[7], tmp7 = d[0] - d[7];
    float tmp1 = d[1] + d[6], tmp6 = d[1] - d[6];
    float tmp2 = d[2] + d[5], tmp5 = d[2] - d[5];
    float tmp3 = d[3] + d[4], tmp4 = d[3] - d[4];

    float tmp10 = tmp0 + tmp3, tmp13 = tmp0 - tmp3;
    float tmp11 = tmp1 + tmp2, tmp12 = tmp1 - tmp2;

    d[0] = tmp10 + tmp11;
    d[4] = tmp10 - tmp11;

    float z1 = (tmp12 + tmp13) * 0.707106781f;
    d[2] = tmp13 + z1;
    d[6] = tmp13 - z1;

    tmp10 = tmp4 + tmp5;
    tmp11 = tmp5 + tmp6;
    tmp12 = tmp6 + tmp7;

    float z5 = (tmp10 - tmp12) * 0.382683433f;
    float z2 = fmaf(0.541196100f, tmp10, z5);
    float z4 = fmaf(1.306562965f, tmp12, z5);
    float z3 = tmp11 * 0.707106781f;

    float z11 = tmp7 + z3;
    float z13 = tmp7 - z3;

    d[5] = z13 + z2;
    d[3] = z13 - z2;
    d[1] = z11 + z4;
    d[7] = z11 - z4;
}

// In-register 8x8 transpose across an 8-lane group (12 shfl butterflies).
__device__ __forceinline__ void transpose8(float* d, int x)
{
    #pragma unroll
    for (int m = 1; m < 8; m <<= 1) {
        #pragma unroll
        for (int j0 = 0; j0 < 8; j0++) {
            if (j0 & m) continue;
            int j1 = j0 | m;
            float a   = (x & m) ? d[j0] : d[j1];
            float bsh = __shfl_xor_sync(0xffffffffu, a, m);
            if (x & m) d[j0] = bsh; else d[j1] = bsh;
        }
    }
}

__constant__ int c_yt[64] = {
    16,11,10,16,24,40,51,61, 12,12,14,19,26,58,60,55,
    14,13,16,24,40,57,69,56, 14,17,22,29,51,87,80,62,
    18,22,37,56,68,109,103,77, 24,35,55,64,81,104,113,92,
    49,64,78,87,103,121,120,101, 72,92,95,98,112,100,103,99};
__constant__ int c_ct[64] = {
    17,18,24,47,99,99,99,99, 18,21,26,66,99,99,99,99,
    24,26,56,99,99,99,99,99, 47,66,99,99,99,99,99,99,
    99,99,99,99,99,99,99,99, 99,99,99,99,99,99,99,99,
    99,99,99,99,99,99,99,99, 99,99,99,99,99,99,99,99};
__constant__ float c_asf[8] = {
    1.0f, 1.3870398453f, 1.3065629649f, 1.1758756024f,
    1.0f, 0.7856949583f, 0.5411961001f, 0.2758993792f};

// One CTA: 64(W) x 32(H) pixel tile -> 32 Y + 8 Cb + 8 Cr blocks
__global__ void __launch_bounds__(256, 8)
jpeg_compress_kernel(const float* __restrict__ img, float* __restrict__ out)
{
    __shared__ float sY  [32][68];   // Y - 128, padded for conflict-free float4
    __shared__ float sCbP[16][36];   // pooled Cb (centered), 32x16
    __shared__ float sCrP[16][36];   // pooled Cr (centered)
    __shared__ float sQ  [128];      // quant reciprocal tables

    const int t       = threadIdx.x;
    const int tileCol = blockIdx.x;   // 0..7   (64-px cols)
    const int tileRow = blockIdx.y;   // 0..15  (32-px rows)
    const int b       = blockIdx.z;
    const int nbatch  = gridDim.z;

    // --- quant tables (pure fp32) ---
    if (t < 64) {
        int uu = t >> 3, vv = t & 7;
        float sc = 1.0f / (8.0f * c_asf[uu] * c_asf[vv]);
        sQ[t]      = sc / (float)c_yt[t];
        sQ[64 + t] = sc / (float)c_ct[t];
    }

    // --- Phase 1: both 16-row subtiles; streaming loads, high MLP ---
    const size_t plane = (size_t)IMG_H * IMG_W;
    const float* base = img + (size_t)b * 3 * plane
                      + (size_t)(tileRow * 32) * IMG_W + tileCol * 64;
    const int r  = t >> 4;           // 0..15 (row within subtile)
    const int c4 = (t & 15) * 4;

    #pragma unroll
    for (int s = 0; s < 2; s++) {
        const float* sb = base + (size_t)(s * 16 + r) * IMG_W + c4;
        const float4 R4 = __ldcs(reinterpret_cast<const float4*>(sb));
        const float4 G4 = __ldcs(reinterpret_cast<const float4*>(sb + plane));
        const float4 B4 = __ldcs(reinterpret_cast<const float4*>(sb + 2 * plane));
        float Rv[4] = {R4.x, R4.y, R4.z, R4.w};
        float Gv[4] = {G4.x, G4.y, G4.z, G4.w};
        float Bv[4] = {B4.x, B4.y, B4.z, B4.w};
        float y[4], cb[4], cr[4];
        #pragma unroll
        for (int i = 0; i < 4; i++) {
            float R = Rv[i] * 255.0f;
            float G = Gv[i] * 255.0f;
            float B = Bv[i] * 255.0f;
            y [i] =  0.299f    * R + 0.587f    * G + 0.114f    * B - 128.0f;
            cb[i] = -0.168736f * R - 0.331264f * G + 0.5f      * B;
            cr[i] =  0.5f      * R - 0.418688f * G - 0.081312f * B;
        }
        *reinterpret_cast<float4*>(&sY[s * 16 + r][c4]) = make_float4(y[0], y[1], y[2], y[3]);

        // horizontal pool in regs, vertical pool via shfl with partner row (lane ^ 16)
        float hcb0 = cb[0] + cb[1], hcb1 = cb[2] + cb[3];
        float hcr0 = cr[0] + cr[1], hcr1 = cr[2] + cr[3];
        float pcb0 = hcb0 + __shfl_xor_sync(0xffffffffu, hcb0, 16);
        float pcb1 = hcb1 + __shfl_xor_sync(0xffffffffu, hcb1, 16);
        float pcr0 = hcr0 + __shfl_xor_sync(0xffffffffu, hcr0, 16);
        float pcr1 = hcr1 + __shfl_xor_sync(0xffffffffu, hcr1, 16);
        if (!(t & 16)) {
            int pr = s * 8 + (r >> 1);
            int pc = (t & 15) * 2;
            *reinterpret_cast<float2*>(&sCbP[pr][pc]) = make_float2(0.25f * pcb0, 0.25f * pcb1);
            *reinterpret_cast<float2*>(&sCrP[pr][pc]) = make_float2(0.25f * pcr0, 0.25f * pcr1);
        }
    }
    __syncthreads();

    // --- Phase 3: 48 blocks. Iter 1: ALL 32 groups do Y blocks (0% idle).
    //     Iter 2: 16 groups do the 8 Cb + 8 Cr blocks. ---
    const int g = t >> 3;   // group 0..31
    const int x = t & 7;

    // ---- Iter 1: Y block g (by = g>>3 in 0..3, bx = g&7) ----
    {
        const int by = g >> 3, bx = g & 7;
        float d[8];
        float4 a = *reinterpret_cast<const float4*>(&sY[by * 8 + x][bx * 8]);
        float4 c = *reinterpret_cast<const float4*>(&sY[by * 8 + x][bx * 8 + 4]);
        d[0]=a.x; d[1]=a.y; d[2]=a.z; d[3]=a.w;
        d[4]=c.x; d[5]=c.y; d[6]=c.z; d[7]=c.w;

        aan_dct8(d);
        transpose8(d, x);
        aan_dct8(d);

        const int v = x;
        int n = (tileRow * 4 + by) * 64 + (tileCol * 8 + bx);
        float* dst = out + (size_t)b * 4096 * 64 + (size_t)n * 64 + v;
        #pragma unroll
        for (int u = 0; u < 8; u++)
            __stcs(dst + u * 8, rintf(d[u] * sQ[u * 8 + v]));
    }

    // ---- Iter 2: chroma block (g < 16): comp = g>>3, idx = g&7 ----
    if (g < 16) {
        const int comp = g >> 3;          // 0 = Cb, 1 = Cr
        const int idx  = g & 7;
        const int byc  = idx >> 2;        // 0..1
        const int bxc  = idx & 3;         // 0..3
        const float (*src)[36] = comp ? sCrP : sCbP;

        float d[8];
        float4 a = *reinterpret_cast<const float4*>(&src[byc * 8 + x][bxc * 8]);
        float4 c = *reinterpret_cast<const float4*>(&src[byc * 8 + x][bxc * 8 + 4]);
        d[0]=a.x; d[1]=a.y; d[2]=a.z; d[3]=a.w;
        d[4]=c.x; d[5]=c.y; d[6]=c.z; d[7]=c.w;

        aan_dct8(d);
        transpose8(d, x);
        aan_dct8(d);

        const int v = x;
        int n = (tileRow * 2 + byc) * 32 + (tileCol * 4 + bxc);
        size_t off = (size_t)nbatch * 4096 * 64
                   + (size_t)comp * nbatch * 1024 * 64
                   + (size_t)b * 1024 * 64 + (size_t)n * 64;
        float* dst = out + off + v;
        #pragma unroll
        for (int u = 0; u < 8; u++)
            __stcs(dst + u * 8, rintf(d[u] * sQ[64 + u * 8 + v]));
    }
}

extern "C" void kernel_launch(void* const* d_in, const int* in_sizes, int n_in,
                              void* d_out, int out_size)
{
    const float* img = (const float*)d_in[0];
    float* out = (float*)d_out;
    int nbatch = in_sizes[0] / (3 * IMG_H * IMG_W);
    dim3 grid(IMG_W / 64, IMG_H / 32, nbatch);
    jpeg_compress_kernel<<<grid, 256>>>(img, out);
}